// round 14
// baseline (speedup 1.0000x reference)
#include <cuda_runtime.h>
#include <cuda_fp16.h>
#include <cstdint>

#define BATCH 4
#define NN 1024
#define LL 64
#define NP 256
#define IMG_PIX (BATCH * NN * NN)

// ---------------- scratch ----------------
__device__ __half2 g_Xh[BATCH * NN * NN];             // half2 spectrum
__device__ __half2 g_S1h[BATCH * LL * NP * NP];       // half2 patch scratch
__device__ float   g_ACC[BATCH * NN * NN * 2];        // fp32 accumulator
__device__ __half2 g_Dh[BATCH * NN * NN];             // half2 D (scaled 1/1024)

// ---------------- packed complex (Blackwell f32x2) ----------------
typedef unsigned long long cplx;

__device__ __forceinline__ cplx mkc(float x, float y){ cplx r; asm("mov.b64 %0,{%1,%2};":"=l"(r):"f"(x),"f"(y)); return r; }
__device__ __forceinline__ void gxy(cplx v, float& x, float& y){ asm("mov.b64 {%0,%1},%2;":"=f"(x),"=f"(y):"l"(v)); }
__device__ __forceinline__ cplx cadd(cplx a, cplx b){ cplx r; asm("add.rn.f32x2 %0,%1,%2;":"=l"(r):"l"(a),"l"(b)); return r; }
__device__ __forceinline__ cplx csub(cplx a, cplx b){
    const cplx NEG1 = 0xBF800000BF800000ULL;
    cplx r; asm("fma.rn.f32x2 %0,%1,%2,%3;":"=l"(r):"l"(b),"l"(NEG1),"l"(a)); return r;   // a - b exactly
}
__device__ __forceinline__ cplx cmulw(cplx a, float2 w){
    float ax, ay; gxy(a, ax, ay);
    return mkc(fmaf(ax, w.x, -ay*w.y), fmaf(ax, w.y, ay*w.x));
}
__device__ __forceinline__ float2 cmulf(float2 a, float2 b){
    return make_float2(fmaf(a.x,b.x,-a.y*b.y), fmaf(a.x,b.y,a.y*b.x));
}
__device__ __forceinline__ float2 conjf2(float2 a){ return make_float2(a.x, -a.y); }
__device__ __forceinline__ cplx h2c(__half2 h){ float2 f = __half22float2(h); return mkc(f.x, f.y); }
__device__ __forceinline__ __half2 c2h(cplx v){ float a,b; gxy(v,a,b); return __floats2half2_rn(a,b); }

// compile-time bit reversals (fold with unrolled constant args)
__device__ __forceinline__ constexpr int br4(int i){
    return ((i&1)<<3) | ((i&2)<<1) | ((i&4)>>1) | ((i&8)>>3);
}
__device__ __forceinline__ constexpr int br5(int i){
    return ((i&1)<<4) | ((i&2)<<2) | (i&4) | ((i&8)>>2) | ((i&16)>>4);
}

// packed float2 global reduction (sm_90+)
__device__ __forceinline__ void red_add_v2(float* addr, float vx, float vy) {
    asm volatile("red.global.add.v2.f32 [%0], {%1, %2};"
                 :: "l"(addr), "f"(vx), "f"(vy) : "memory");
}

// ---------------- in-place DIF16: natural in, bit-reversed out (X[k] at r[br4(k)]) ----------------
template<int SGN>
__device__ __forceinline__ void dif16(cplx* r) {
    const float C1 = 0.923879532511287f, S1 = 0.382683432365090f, C2 = 0.707106781186548f;
    const float2 W[8] = {
        {1.f, 0.f}, {C1, SGN*S1}, {C2, SGN*C2}, {S1, SGN*C1},
        {0.f, SGN*1.f}, {-S1, SGN*C1}, {-C2, SGN*C2}, {-C1, SGN*S1}
    };
    #pragma unroll
    for (int k = 0; k < 8; ++k) {               // h=8, twiddle W[k]
        cplx u = cadd(r[k], r[k+8]);
        cplx v = csub(r[k], r[k+8]);
        r[k]   = u;
        r[k+8] = cmulw(v, W[k]);
    }
    #pragma unroll
    for (int b = 0; b < 2; ++b)                 // h=4, twiddle W[2k]
        #pragma unroll
        for (int k = 0; k < 4; ++k) {
            int i = b*8 + k;
            cplx u = cadd(r[i], r[i+4]);
            cplx v = csub(r[i], r[i+4]);
            r[i]   = u;
            r[i+4] = cmulw(v, W[2*k]);
        }
    #pragma unroll
    for (int b = 0; b < 4; ++b)                 // h=2, twiddle W[4k]
        #pragma unroll
        for (int k = 0; k < 2; ++k) {
            int i = b*4 + k;
            cplx u = cadd(r[i], r[i+2]);
            cplx v = csub(r[i], r[i+2]);
            r[i]   = u;
            r[i+2] = cmulw(v, W[4*k]);
        }
    #pragma unroll
    for (int b = 0; b < 8; ++b) {               // h=1
        int i = b*2;
        cplx u = cadd(r[i], r[i+1]);
        cplx v = csub(r[i], r[i+1]);
        r[i]   = u;
        r[i+1] = v;
    }
}

// ---------------- in-place DIF32: natural in, bit-reversed out (X[k] at r[br5(k)]) ----------------
template<int SGN>
__device__ __forceinline__ void dif32(cplx* r) {
    const float A1 = 0.980785280403230f, B1 = 0.195090322016128f;
    const float A2 = 0.923879532511287f, B2 = 0.382683432365090f;
    const float A3 = 0.831469612302545f, B3 = 0.555570233019602f;
    const float A4 = 0.707106781186548f;
    const float2 W[16] = {
        {1.f, 0.f},      {A1, SGN*B1},   {A2, SGN*B2},   {A3, SGN*B3},
        {A4, SGN*A4},    {B3, SGN*A3},   {B2, SGN*A2},   {B1, SGN*A1},
        {0.f, SGN*1.f},  {-B1, SGN*A1},  {-B2, SGN*A2},  {-B3, SGN*A3},
        {-A4, SGN*A4},   {-A3, SGN*B3},  {-A2, SGN*B2},  {-A1, SGN*B1}
    };
    #pragma unroll
    for (int k = 0; k < 16; ++k) {              // h=16, W[k]
        cplx u = cadd(r[k], r[k+16]);
        cplx v = csub(r[k], r[k+16]);
        r[k]    = u;
        r[k+16] = cmulw(v, W[k]);
    }
    #pragma unroll
    for (int b = 0; b < 2; ++b)                 // h=8, W[2k]
        #pragma unroll
        for (int k = 0; k < 8; ++k) {
            int i = b*16 + k;
            cplx u = cadd(r[i], r[i+8]);
            cplx v = csub(r[i], r[i+8]);
            r[i]   = u;
            r[i+8] = cmulw(v, W[2*k]);
        }
    #pragma unroll
    for (int b = 0; b < 4; ++b)                 // h=4, W[4k]
        #pragma unroll
        for (int k = 0; k < 4; ++k) {
            int i = b*8 + k;
            cplx u = cadd(r[i], r[i+4]);
            cplx v = csub(r[i], r[i+4]);
            r[i]   = u;
            r[i+4] = cmulw(v, W[4*k]);
        }
    #pragma unroll
    for (int b = 0; b < 8; ++b)                 // h=2, W[8k]
        #pragma unroll
        for (int k = 0; k < 2; ++k) {
            int i = b*4 + k;
            cplx u = cadd(r[i], r[i+2]);
            cplx v = csub(r[i], r[i+2]);
            r[i]   = u;
            r[i+2] = cmulw(v, W[8*k]);
        }
    #pragma unroll
    for (int b = 0; b < 16; ++b) {              // h=1
        int i = b*2;
        cplx u = cadd(r[i], r[i+1]);
        cplx v = csub(r[i], r[i+1]);
        r[i]   = u;
        r[i+1] = v;
    }
}

// chain-split twiddle stores; coefficient k1 lives at x[br(k1)] (DIF output)
__device__ __forceinline__ void tw_store16(cplx* S, int ST, int t, const cplx* x, float2 w1) {
    float2 w2 = cmulf(w1, w1);
    float2 w4 = cmulf(w2, w2);
    float2 w8 = cmulf(w4, w4);
    float2 wA = make_float2(1.f, 0.f), wB = w4, wC = w8, wD = cmulf(w8, w4);
    #pragma unroll
    for (int b = 0; b < 4; ++b) {
        S[(b)     * ST + t] = (b == 0) ? x[0] : cmulw(x[br4(b)], wA);
        S[(b + 4) * ST + t] = cmulw(x[br4(b + 4)],  wB);
        S[(b + 8) * ST + t] = cmulw(x[br4(b + 8)],  wC);
        S[(b + 12)* ST + t] = cmulw(x[br4(b + 12)], wD);
        if (b == 0) wA = w1; else wA = cmulf(wA, w1);
        wB = cmulf(wB, w1);
        wC = cmulf(wC, w1);
        wD = cmulf(wD, w1);
    }
}

__device__ __forceinline__ void tw_store32(cplx* S, int ST, int t, const cplx* x, float2 w1) {
    float2 w2  = cmulf(w1, w1);
    float2 w4  = cmulf(w2, w2);
    float2 w8  = cmulf(w4, w4);
    float2 w16 = cmulf(w8, w8);
    float2 wA = make_float2(1.f, 0.f), wB = w8, wC = w16, wD = cmulf(w16, w8);
    #pragma unroll
    for (int b = 0; b < 8; ++b) {
        S[(b)      * ST + t] = (b == 0) ? x[0] : cmulw(x[br5(b)], wA);
        S[(b + 8)  * ST + t] = cmulw(x[br5(b + 8)],   wB);
        S[(b + 16) * ST + t] = cmulw(x[br5(b + 16)],  wC);
        S[(b + 24) * ST + t] = cmulw(x[br5(b + 24)],  wD);
        if (b == 0) wA = w1; else wA = cmulf(wA, w1);
        wB = cmulf(wB, w1);
        wC = cmulf(wC, w1);
        wD = cmulf(wD, w1);
    }
}

__device__ __forceinline__ void tw_store16_p2(cplx* S, int t, int c, const cplx* x, float2 w1) {
    float2 w2 = cmulf(w1, w1);
    float2 w4 = cmulf(w2, w2);
    float2 w8 = cmulf(w4, w4);
    float2 wA = make_float2(1.f, 0.f), wB = w4, wC = w8, wD = cmulf(w8, w4);
    int base = t*16 + c;
    #pragma unroll
    for (int b = 0; b < 4; ++b) {
        S[(b)     * 256 + base] = (b == 0) ? x[0] : cmulw(x[br4(b)], wA);
        S[(b + 4) * 256 + base] = cmulw(x[br4(b + 4)],  wB);
        S[(b + 8) * 256 + base] = cmulw(x[br4(b + 8)],  wC);
        S[(b + 12)* 256 + base] = cmulw(x[br4(b + 12)], wD);
        if (b == 0) wA = w1; else wA = cmulf(wA, w1);
        wB = cmulf(wB, w1);
        wC = cmulf(wC, w1);
        wD = cmulf(wD, w1);
    }
}

// ================= 1024-pt kernels =================

__global__ __launch_bounds__(128) void k_rows_fwd_planar(const float* __restrict__ re, const float* __restrict__ im) {
    __shared__ cplx S[4 * 1056];
    int tid = threadIdx.x;
    int r = tid >> 5, t = tid & 31;
    int row = blockIdx.x * 4 + r;
    const float* rp = re + (size_t)row * NN;
    const float* ip = im + (size_t)row * NN;
    cplx x[32];
    #pragma unroll
    for (int m = 0; m < 32; ++m) x[m] = mkc(rp[m*32 + t], ip[m*32 + t]);
    dif32<-1>(x);
    float ss, cc; sincospif(-(float)t / 512.0f, &ss, &cc);
    tw_store32(S + r * 1056, 33, t, x, make_float2(cc, ss));
    __syncthreads();
    cplx y[32];
    cplx* Sr = S + r * 1056;
    #pragma unroll
    for (int n2 = 0; n2 < 32; ++n2) y[n2] = Sr[t*33 + n2];
    dif32<-1>(y);
    __half2* o = g_Xh + (size_t)row * NN;
    #pragma unroll
    for (int k2 = 0; k2 < 32; ++k2) o[t + 32*k2] = c2h(y[br5(k2)]);
}

// rows_inv: reads ACC, re-zeroes it, writes D/1024 into g_Dh
__global__ __launch_bounds__(128) void k_rows_inv_acc() {
    __shared__ cplx S[4 * 1056];
    int tid = threadIdx.x;
    int r = tid >> 5, t = tid & 31;
    int row = blockIdx.x * 4 + r;
    cplx* src = ((cplx*)g_ACC) + (size_t)row * NN;
    cplx x[32];
    #pragma unroll
    for (int m = 0; m < 32; ++m) x[m] = src[m*32 + t];
    #pragma unroll
    for (int m = 0; m < 32; ++m) src[m*32 + t] = 0ULL;
    dif32<+1>(x);
    float ss, cc; sincospif((float)t / 512.0f, &ss, &cc);
    tw_store32(S + r * 1056, 33, t, x, make_float2(cc, ss));
    __syncthreads();
    cplx y[32];
    cplx* Sr = S + r * 1056;
    #pragma unroll
    for (int n2 = 0; n2 < 32; ++n2) y[n2] = Sr[t*33 + n2];
    dif32<+1>(y);
    __half2* o = g_Dh + (size_t)row * NN;
    const float dsc = 1.0f / 1024.0f;
    #pragma unroll
    for (int k2 = 0; k2 < 32; ++k2) {
        float a, bb; gxy(y[br5(k2)], a, bb);
        o[t + 32*k2] = __floats2half2_rn(a * dsc, bb * dsc);
    }
}

#define COLS_SMEM_BYTES (8 * 1058 * (int)sizeof(cplx))

__global__ __launch_bounds__(256) void k_cols_fwd_X() {
    extern __shared__ cplx S[];
    int tid = threadIdx.x;
    int c = tid & 7, t = tid >> 3;
    int b  = blockIdx.x >> 7;
    int c0 = (blockIdx.x & 127) * 8;
    __half2* img = g_Xh + (size_t)b * NN * NN;
    cplx x[32];
    #pragma unroll
    for (int m = 0; m < 32; ++m) x[m] = h2c(img[(size_t)(m*32 + t) * NN + c0 + c]);
    dif32<-1>(x);
    float ss, cc; sincospif(-(float)t / 512.0f, &ss, &cc);
    tw_store32(S + c * 1058, 33, t, x, make_float2(cc, ss));
    __syncthreads();
    cplx y[32];
    cplx* Sc = S + c * 1058;
    #pragma unroll
    for (int n2 = 0; n2 < 32; ++n2) y[n2] = Sc[t*33 + n2];
    dif32<-1>(y);
    #pragma unroll
    for (int k2 = 0; k2 < 32; ++k2) img[(size_t)(t + 32*k2) * NN + c0 + c] = c2h(y[br5(k2)]);
}

__global__ __launch_bounds__(256) void k_cols_inv_final(const float* __restrict__ img_a, const float* __restrict__ xre,
                                 const float* __restrict__ xim,  const float* __restrict__ lamb,
                                 const float* __restrict__ eta1, float* __restrict__ out,
                                 long long out_size) {
    extern __shared__ cplx S[];
    int tid = threadIdx.x;
    int c = tid & 7, t = tid >> 3;
    int b  = blockIdx.x >> 7;
    int c0 = (blockIdx.x & 127) * 8;
    const __half2* img = g_Dh + (size_t)b * NN * NN;
    cplx x[32];
    #pragma unroll
    for (int m = 0; m < 32; ++m) x[m] = h2c(img[(size_t)(m*32 + t) * NN + c0 + c]);
    dif32<+1>(x);
    float ss, cc; sincospif((float)t / 512.0f, &ss, &cc);
    tw_store32(S + c * 1058, 33, t, x, make_float2(cc, ss));
    __syncthreads();
    cplx y[32];
    cplx* Sc = S + c * 1058;
    #pragma unroll
    for (int n2 = 0; n2 < 32; ++n2) y[n2] = Sc[t*33 + n2];
    dif32<+1>(y);
    float e1  = eta1[0];
    float lm  = lamb[0];
    float bco = 100.0f * e1 * lm;
    float aco = 10.0f  * e1;
    float coef = aco / ((float)LL * 1024.0f);     // D stored pre-scaled 1/1024
    float one_m_b = 1.0f - bco;
    #pragma unroll
    for (int k2 = 0; k2 < 32; ++k2) {
        int rrow = t + 32*k2;
        long long idx = ((long long)b * NN + rrow) * NN + c0 + c;
        float dx, dy; gxy(y[br5(k2)], dx, dy);
        float xr = xre[idx], xi = xim[idx];
        float m  = sqrtf(fmaf(xr, xr, xi * xi)) + 1e-6f;
        float fa = bco * img_a[idx] / m;
        float rcx = one_m_b * xr - coef * dx + fa * xr;
        float rcy = one_m_b * xi - coef * dy + fa * xi;
        if (idx < out_size) out[idx] = sqrtf(fmaf(rcx, rcx, rcy * rcy));
        long long ore = (long long)IMG_PIX + idx;
        long long oim = (long long)(2 * IMG_PIX) + idx;
        if (ore < out_size) out[ore] = rcx;
        if (oim < out_size) out[oim] = rcy;
    }
}

// ================= patch kernels =================

__global__ __launch_bounds__(256) void k_p1(const int* __restrict__ masks, const float* __restrict__ ctf) {
    __shared__ cplx S[16 * 272];
    int tid = threadIdx.x;
    int r = tid >> 4, t = tid & 15;
    int rg = blockIdx.x & 15;
    int pk = blockIdx.x >> 4;
    int b  = pk >> 6, k = pk & 63;
    int mr = masks[2*k] - 1, mc = masks[2*k+1] - 1;
    int i  = (rg << 4) + r;
    int gr = (mr + i + 512) & 1023;
    const __half2* Xrow = g_Xh + ((size_t)b * NN + gr) * NN;
    const float*  cfr  = ctf + i * NP;
    cplx x[16];
    const float sc = 1.0f / 256.0f;
    #pragma unroll
    for (int m = 0; m < 16; ++m) {
        int j  = m*16 + t;
        int gc = (mc + j + 512) & 1023;
        float2 v = __half22float2(Xrow[gc]);
        float cf = cfr[j] * sc;
        x[m] = mkc(v.x * cf, v.y * cf);
    }
    dif16<+1>(x);
    float ss, cc; sincospif(2.0f * (float)t / 256.0f, &ss, &cc);
    tw_store16(S + r * 272, 17, t, x, make_float2(cc, ss));
    __syncthreads();
    cplx y[16];
    cplx* Sr = S + r * 272;
    #pragma unroll
    for (int n2 = 0; n2 < 16; ++n2) y[n2] = Sr[t*17 + n2];
    dif16<+1>(y);
    __half2* o = g_S1h + ((size_t)pk * NP + i) * NP;
    #pragma unroll
    for (int k2 = 0; k2 < 16; ++k2) o[t + 16*k2] = c2h(y[br4(k2)]);
}

__global__ __launch_bounds__(256) void k_p2(const float* __restrict__ Y) {
    __shared__ cplx S[16 * 256];
    __shared__ float Ysm[256 * 16];
    int tid = threadIdx.x;
    int t = tid >> 4, c = tid & 15;
    int pk = blockIdx.x >> 4;
    int c0 = (blockIdx.x & 15) << 4;
    const float* Yp = Y + (size_t)pk * NP * NP;
    #pragma unroll
    for (int q = 0; q < 16; ++q) {
        int idx = tid + q * 256;
        int row = idx >> 4, col = idx & 15;
        Ysm[idx] = Yp[row * NP + c0 + col];
    }
    __half2* P = g_S1h + (size_t)pk * NP * NP;
    cplx x[16];
    #pragma unroll
    for (int m = 0; m < 16; ++m) x[m] = h2c(P[(m*16 + t) * NP + c0 + c]);
    dif16<+1>(x);
    float ss, cc; sincospif(2.0f * (float)t / 256.0f, &ss, &cc);
    float2 w1inv = make_float2(cc, ss);
    tw_store16_p2(S, t, c, x, w1inv);
    __syncthreads();
    cplx y[16];
    #pragma unroll
    for (int n2 = 0; n2 < 16; ++n2) y[n2] = S[t*256 + n2*16 + c];
    dif16<+1>(y);
    // projection into natural-order array pr[] (spatial row k2 lives at y[br4(k2)])
    const float inv = 1.0f / 256.0f;
    cplx pr[16];
    #pragma unroll
    for (int k2 = 0; k2 < 16; ++k2) {
        float wx, wy; gxy(y[br4(k2)], wx, wy);
        wx *= inv; wy *= inv;
        float mag2 = fmaf(wx, wx, wy * wy);
        float yv   = Ysm[(t + 16*k2) * 16 + c];
        if (mag2 > 0.0f) {
            float f = 1.0f - sqrtf(__fdividef(yv, mag2));
            pr[k2] = mkc(wx * f, wy * f);
        } else {
            pr[k2] = mkc(-sqrtf(yv), 0.0f);
        }
    }
    dif16<-1>(pr);
    __syncthreads();
    tw_store16_p2(S, t, c, pr, conjf2(w1inv));
    __syncthreads();
    cplx z[16];
    #pragma unroll
    for (int n2 = 0; n2 < 16; ++n2) z[n2] = S[t*256 + n2*16 + c];
    dif16<-1>(z);
    #pragma unroll
    for (int k2 = 0; k2 < 16; ++k2) P[(t + 16*k2) * NP + c0 + c] = c2h(z[br4(k2)]);
}

__global__ __launch_bounds__(256) void k_p3(const int* __restrict__ masks, const float* __restrict__ ctf) {
    __shared__ cplx S[16 * 272];
    int tid = threadIdx.x;
    int r = tid >> 4, t = tid & 15;
    int rg = blockIdx.x & 15;
    int pk = blockIdx.x >> 4;
    int b  = pk >> 6, k = pk & 63;
    int mr = masks[2*k] - 1, mc = masks[2*k+1] - 1;
    int i  = (rg << 4) + r;
    const __half2* src = g_S1h + ((size_t)pk * NP + i) * NP;
    cplx x[16];
    #pragma unroll
    for (int m = 0; m < 16; ++m) x[m] = h2c(src[m*16 + t]);
    dif16<-1>(x);
    float ss, cc; sincospif(-2.0f * (float)t / 256.0f, &ss, &cc);
    tw_store16(S + r * 272, 17, t, x, make_float2(cc, ss));
    __syncthreads();
    cplx y[16];
    cplx* Sr = S + r * 272;
    #pragma unroll
    for (int n2 = 0; n2 < 16; ++n2) y[n2] = Sr[t*17 + n2];
    dif16<-1>(y);
    int gr = (mr + i + 512) & 1023;
    float* accrow = g_ACC + ((size_t)b * NN + gr) * NN * 2;
    const float* cfr = ctf + i * NP;
    #pragma unroll
    for (int k2 = 0; k2 < 16; ++k2) {
        int j  = t + 16*k2;
        float cf = cfr[j];
        float a, bb; gxy(y[br4(k2)], a, bb);
        int gc = (mc + j + 512) & 1023;
        red_add_v2(accrow + gc*2, a * cf, bb * cf);
    }
}

// ---------------- launch ----------------
extern "C" void kernel_launch(void* const* d_in, const int* in_sizes, int n_in,
                              void* d_out, int out_size) {
    const float* Img_a = (const float*)d_in[0];
    const float* Xre   = (const float*)d_in[1];
    const float* Xim   = (const float*)d_in[2];
    const float* Y     = (const float*)d_in[3];
    const int*   Masks = (const int*)  d_in[4];
    const float* CTF   = (const float*)d_in[5];
    const float* lamb  = (const float*)d_in[6];
    const float* eta1  = (const float*)d_in[7];
    float* out = (float*)d_out;

    cudaFuncSetAttribute((const void*)k_cols_fwd_X,
                         cudaFuncAttributeMaxDynamicSharedMemorySize, COLS_SMEM_BYTES);
    cudaFuncSetAttribute((const void*)k_cols_inv_final,
                         cudaFuncAttributeMaxDynamicSharedMemorySize, COLS_SMEM_BYTES);

    k_rows_fwd_planar<<<BATCH * NN / 4, 128>>>(Xre, Xim);
    k_cols_fwd_X<<<BATCH * 128, 256, COLS_SMEM_BYTES>>>();
    k_p1<<<BATCH * LL * 16, 256>>>(Masks, CTF);
    k_p2<<<BATCH * LL * 16, 256>>>(Y);
    k_p3<<<BATCH * LL * 16, 256>>>(Masks, CTF);
    k_rows_inv_acc<<<BATCH * NN / 4, 128>>>();
    k_cols_inv_final<<<BATCH * 128, 256, COLS_SMEM_BYTES>>>(
        Img_a, Xre, Xim, lamb, eta1, out, (long long)out_size);
}